// round 5
// baseline (speedup 1.0000x reference)
#include <cuda_runtime.h>
#include <cuda_bf16.h>
#include <math.h>
#include <stdint.h>

#define NN 50000
#define EE 800000

// ================= scratch (device globals) =================
__device__ float g_emb[(size_t)NN * 256];   // [x | h1 | h2 | h3]
__device__ float g_t[(size_t)NN * 64];      // pre-mlp intermediate
__device__ float g_yr[(size_t)NN * 128];    // per-layer [y | r]
__device__ unsigned short g_Bh[192 * 128];  // B hi, mma-fragment order
__device__ unsigned short g_Bl[192 * 128];  // B lo, mma-fragment order
__device__ int   g_cnt[NN];
__device__ int   g_rowptr[NN];
__device__ int   g_cursor[NN];
__device__ int   g_csr_src[EE];
__device__ float g_invdeg[NN];
__device__ float g_s[256];

// ================= setup =================
__global__ void zero_kernel() {
    int i = blockIdx.x * blockDim.x + threadIdx.x;
    if (i < NN) g_cnt[i] = 0;
    if (i < 256) g_s[i] = 0.f;
}
__global__ void hist_kernel(const int* __restrict__ ei) {
    int e = blockIdx.x * blockDim.x + threadIdx.x;
    if (e < EE) atomicAdd(&g_cnt[ei[EE + e]], 1);
}
__global__ void scan_kernel() {
    __shared__ int partial[1024];
    const int CH = (NN + 1023) / 1024;
    int tid = threadIdx.x;
    int start = tid * CH;
    int sum = 0;
    for (int i = 0; i < CH; i++) { int idx = start + i; if (idx < NN) sum += g_cnt[idx]; }
    partial[tid] = sum;
    __syncthreads();
    for (int off = 1; off < 1024; off <<= 1) {
        int add = (tid >= off) ? partial[tid - off] : 0;
        __syncthreads();
        partial[tid] += add;
        __syncthreads();
    }
    int base = (tid == 0) ? 0 : partial[tid - 1];
    for (int i = 0; i < CH; i++) {
        int idx = start + i;
        if (idx < NN) {
            int c = g_cnt[idx];
            g_rowptr[idx] = base;
            g_cursor[idx] = base;
            g_invdeg[idx] = 1.0f / (float)(c > 1 ? c : 1);
            base += c;
        }
    }
}
__global__ void scatter_kernel(const int* __restrict__ ei) {
    int e = blockIdx.x * blockDim.x + threadIdx.x;
    if (e < EE) {
        int dst = ei[EE + e];
        int pos = atomicAdd(&g_cursor[dst], 1);
        g_csr_src[pos] = ei[e];
    }
}

// ================= pack B into m16n8k16 fragment order (hi/lo bf16) =================
__global__ void packB_kernel(const float* __restrict__ wl, const float* __restrict__ wr,
                             const float* __restrict__ skip, int layer, int K, int NTILE) {
    int idx = blockIdx.x * blockDim.x + threadIdx.x;
    if (idx >= K * NTILE) return;
    int k = idx / NTILE, n = idx - k * NTILE;
    float w;
    if (wr) {
        float g = 1.f / (1.f + expf(-skip[layer * 3 + (k >> 6)]));
        w = ((n < 64) ? wl[k * 64 + n] : wr[k * 64 + (n - 64)]) * g;
    } else {
        w = wl[k * NTILE + n];
    }
    int kc = k >> 4, kin = k & 15, nc = n >> 3, nin = n & 7;
    int lane = nin * 4 + ((kin & 7) >> 1);
    int reg = kin >> 3, half = kin & 1;
    int hidx = (((kc * (NTILE >> 3) + nc) * 32 + lane) * 2 + reg) * 2 + half;
    __nv_bfloat16 hi = __float2bfloat16(w);
    __nv_bfloat16 lo = __float2bfloat16(w - __bfloat162float(hi));
    g_Bh[hidx] = __bfloat16_as_ushort(hi);
    g_Bl[hidx] = __bfloat16_as_ushort(lo);
}

// ================= HMMA GEMM: C[M,NTILE] = act(A[M,K] @ B + bias) =================
__device__ __forceinline__ void mma16816(float* acc, const uint32_t* a,
                                         uint32_t b0, uint32_t b1) {
    asm volatile(
        "mma.sync.aligned.m16n8k16.row.col.f32.bf16.bf16.f32 "
        "{%0,%1,%2,%3}, {%4,%5,%6,%7}, {%8,%9}, {%0,%1,%2,%3};"
        : "+f"(acc[0]), "+f"(acc[1]), "+f"(acc[2]), "+f"(acc[3])
        : "r"(a[0]), "r"(a[1]), "r"(a[2]), "r"(a[3]), "r"(b0), "r"(b1));
}
__device__ __forceinline__ void split2(float x, float y, uint32_t& hi, uint32_t& lo) {
    __nv_bfloat16 hx = __float2bfloat16(x), hy = __float2bfloat16(y);
    __nv_bfloat16 lx = __float2bfloat16(x - __bfloat162float(hx));
    __nv_bfloat16 ly = __float2bfloat16(y - __bfloat162float(hy));
    hi = ((uint32_t)__bfloat16_as_ushort(hy) << 16) | __bfloat16_as_ushort(hx);
    lo = ((uint32_t)__bfloat16_as_ushort(ly) << 16) | __bfloat16_as_ushort(lx);
}

template <int NTILE>
__global__ void __launch_bounds__(256) mma_gemm_kernel(
    const float* __restrict__ A, int lda, int K,
    const float* __restrict__ bias, int act,
    float* __restrict__ C, int ldc, int M) {
    constexpr int NFRAG = NTILE / 8;
    const int tid = threadIdx.x;
    const int wid = tid >> 5, lane = tid & 31;
    const int q = lane & 3, tq = lane >> 2;
    const int r0 = blockIdx.x * 128 + wid * 16 + tq;
    const int r1 = r0 + 8;

    float acc[NFRAG][4];
#pragma unroll
    for (int i = 0; i < NFRAG; i++)
#pragma unroll
        for (int j = 0; j < 4; j++) acc[i][j] = 0.f;

    const uint32_t* __restrict__ Bh = (const uint32_t*)g_Bh;
    const uint32_t* __restrict__ Bl = (const uint32_t*)g_Bl;

    for (int kc = 0; kc < K / 16; kc++) {
        const int c0 = kc * 16 + 2 * q;
        float2 v00 = make_float2(0.f, 0.f), v10 = v00, v01 = v00, v11 = v00;
        if (r0 < M) {
            v00 = *(const float2*)&A[(size_t)r0 * lda + c0];
            v01 = *(const float2*)&A[(size_t)r0 * lda + c0 + 8];
        }
        if (r1 < M) {
            v10 = *(const float2*)&A[(size_t)r1 * lda + c0];
            v11 = *(const float2*)&A[(size_t)r1 * lda + c0 + 8];
        }
        uint32_t ah[4], al[4];
        split2(v00.x, v00.y, ah[0], al[0]);
        split2(v10.x, v10.y, ah[1], al[1]);
        split2(v01.x, v01.y, ah[2], al[2]);
        split2(v11.x, v11.y, ah[3], al[3]);

        const int base = kc * NFRAG * 64 + lane * 2;
#pragma unroll
        for (int nc = 0; nc < NFRAG; nc++) {
            int bi = base + nc * 64;
            uint32_t bh0 = Bh[bi], bh1 = Bh[bi + 1];
            uint32_t bl0 = Bl[bi], bl1 = Bl[bi + 1];
            mma16816(acc[nc], ah, bh0, bh1);
            mma16816(acc[nc], ah, bl0, bl1);
            mma16816(acc[nc], al, bh0, bh1);
        }
    }

#pragma unroll
    for (int nc = 0; nc < NFRAG; nc++) {
        int col = nc * 8 + 2 * q;
        float b0v = bias ? bias[col] : 0.f;
        float b1v = bias ? bias[col + 1] : 0.f;
        if (r0 < M) {
            float x = acc[nc][0] + b0v, y = acc[nc][1] + b1v;
            if (act) { x = fmaxf(x, 0.f); y = fmaxf(y, 0.f); }
            *(float2*)&C[(size_t)r0 * ldc + col] = make_float2(x, y);
        }
        if (r1 < M) {
            float x = acc[nc][2] + b0v, y = acc[nc][3] + b1v;
            if (act) { x = fmaxf(x, 0.f); y = fmaxf(y, 0.f); }
            *(float2*)&C[(size_t)r1 * ldc + col] = make_float2(x, y);
        }
    }
}

// ================= aggregation: one warp per node, 4-way ILP =================
__global__ void agg_kernel(const float* __restrict__ bl, int outcol) {
    int gw = (blockIdx.x * blockDim.x + threadIdx.x) >> 5;
    int lane = threadIdx.x & 31;
    if (gw >= NN) return;
    const int n = gw;
    const int beg = g_rowptr[n], cnt = g_cnt[n];
    const float* __restrict__ yr = g_yr;

    float sx0 = 0.f, sy0 = 0.f, sx1 = 0.f, sy1 = 0.f;
    float sx2 = 0.f, sy2 = 0.f, sx3 = 0.f, sy3 = 0.f;
    int k = 0;
    for (; k + 4 <= cnt; k += 4) {
        // 4 independent gathers in flight
        int s0 = g_csr_src[beg + k];
        int s1 = g_csr_src[beg + k + 1];
        int s2 = g_csr_src[beg + k + 2];
        int s3 = g_csr_src[beg + k + 3];
        float2 v0 = *reinterpret_cast<const float2*>(&yr[(size_t)s0 * 128 + 2 * lane]);
        float2 v1 = *reinterpret_cast<const float2*>(&yr[(size_t)s1 * 128 + 2 * lane]);
        float2 v2 = *reinterpret_cast<const float2*>(&yr[(size_t)s2 * 128 + 2 * lane]);
        float2 v3 = *reinterpret_cast<const float2*>(&yr[(size_t)s3 * 128 + 2 * lane]);
        sx0 += v0.x; sy0 += v0.y;
        sx1 += v1.x; sy1 += v1.y;
        sx2 += v2.x; sy2 += v2.y;
        sx3 += v3.x; sy3 += v3.y;
    }
    for (; k < cnt; k++) {
        int s0 = g_csr_src[beg + k];
        float2 v0 = *reinterpret_cast<const float2*>(&yr[(size_t)s0 * 128 + 2 * lane]);
        sx0 += v0.x; sy0 += v0.y;
    }
    float sx = (sx0 + sx1) + (sx2 + sx3);
    float sy = (sy0 + sy1) + (sy2 + sy3);

    float inv = g_invdeg[n];
    float2 r = *reinterpret_cast<const float2*>(&yr[(size_t)n * 128 + 64 + 2 * lane]);
    float h0 = fmaxf(sx * inv + bl[2 * lane] + r.x, 0.f);
    float h1 = fmaxf(sy * inv + bl[2 * lane + 1] + r.y, 0.f);
    g_emb[(size_t)n * 256 + outcol + 2 * lane] = h0;
    g_emb[(size_t)n * 256 + outcol + 2 * lane + 1] = h1;
}

// ================= column sum + post mlp =================
__global__ void colsum_kernel() {
    int c = threadIdx.x;
    int per = (NN + gridDim.x - 1) / gridDim.x;
    int n0 = blockIdx.x * per;
    int n1 = n0 + per;
    if (n1 > NN) n1 = NN;
    float s = 0.f;
    for (int n = n0; n < n1; n++) s += g_emb[(size_t)n * 256 + c];
    atomicAdd(&g_s[c], s);
}
__global__ void post_kernel(const float* __restrict__ w1, const float* __restrict__ b1,
                            const float* __restrict__ w2, const float* __restrict__ b2,
                            const float* __restrict__ w3, const float* __restrict__ b3,
                            const float* __restrict__ w4, const float* __restrict__ b4,
                            float* __restrict__ out) {
    __shared__ float s1[64], s2[64], s3[256];
    int t = threadIdx.x;
    if (t < 64) {
        float a = b1[t];
        for (int k = 0; k < 256; k++) a += g_s[k] * w1[k * 64 + t];
        s1[t] = (a > 0.f) ? a : 0.1f * a;
    }
    __syncthreads();
    if (t < 64) {
        float a = b2[t];
        for (int k = 0; k < 64; k++) a += s1[k] * w2[k * 64 + t];
        s2[t] = fmaxf(a, 0.f);
    }
    __syncthreads();
    {
        float a = b3[t];
        for (int k = 0; k < 64; k++) a += s2[k] * w3[k * 256 + t];
        s3[t] = fmaxf(a, 0.f);
    }
    __syncthreads();
    if (t < 64) {
        float a = b4[t];
        for (int k = 0; k < 256; k++) a += s3[k] * w4[k * 64 + t];
        out[t] = a;
    }
}

// ================= launch =================
extern "C" void kernel_launch(void* const* d_in, const int* in_sizes, int n_in,
                              void* d_out, int out_size) {
    const float* node_features = (const float*)d_in[0];
    const int*   edge_index    = (const int*)d_in[1];
    const float* pre_w1 = (const float*)d_in[2];
    const float* pre_b1 = (const float*)d_in[3];
    const float* pre_w2 = (const float*)d_in[4];
    const float* pre_b2 = (const float*)d_in[5];
    const float* skip   = (const float*)d_in[6];
    const float* wl[3] = {(const float*)d_in[7], (const float*)d_in[10], (const float*)d_in[13]};
    const float* bl[3] = {(const float*)d_in[8], (const float*)d_in[11], (const float*)d_in[14]};
    const float* wr[3] = {(const float*)d_in[9], (const float*)d_in[12], (const float*)d_in[15]};
    const float* post_w1 = (const float*)d_in[16];
    const float* post_b1 = (const float*)d_in[17];
    const float* post_w2 = (const float*)d_in[18];
    const float* post_b2 = (const float*)d_in[19];
    const float* post_w3 = (const float*)d_in[20];
    const float* post_b3 = (const float*)d_in[21];
    const float* post_w4 = (const float*)d_in[22];
    const float* post_b4 = (const float*)d_in[23];
    float* out = (float*)d_out;

    float *p_t, *p_emb, *p_yr;
    cudaGetSymbolAddress((void**)&p_t, g_t);
    cudaGetSymbolAddress((void**)&p_emb, g_emb);
    cudaGetSymbolAddress((void**)&p_yr, g_yr);

    // CSR build
    zero_kernel<<<(NN + 255) / 256, 256>>>();
    hist_kernel<<<(EE + 255) / 256, 256>>>(edge_index);
    scan_kernel<<<1, 1024>>>();
    scatter_kernel<<<(EE + 255) / 256, 256>>>(edge_index);

    const int MB = (NN + 127) / 128;  // 391

    // pre-mlp GEMM 1: t = relu(X @ pre_w1 + b1), K=128 N=64
    packB_kernel<<<(128 * 64 + 255) / 256, 256>>>(pre_w1, nullptr, nullptr, 0, 128, 64);
    mma_gemm_kernel<64><<<MB, 256>>>(node_features, 128, 128, pre_b1, 1, p_t, 64, NN);
    // pre-mlp GEMM 2: emb[:,0:64] = t @ pre_w2 + b2, K=64 N=64
    packB_kernel<<<(64 * 64 + 255) / 256, 256>>>(pre_w2, nullptr, nullptr, 0, 64, 64);
    mma_gemm_kernel<64><<<MB, 256>>>(p_t, 64, 64, pre_b2, 0, p_emb, 256, NN);

    for (int layer = 0; layer < 3; layer++) {
        int K = 64 * (layer + 1);
        packB_kernel<<<(K * 128 + 255) / 256, 256>>>(wl[layer], wr[layer], skip, layer, K, 128);
        mma_gemm_kernel<128><<<MB, 256>>>(p_emb, 256, K, (const float*)nullptr, 0, p_yr, 128, NN);
        agg_kernel<<<(NN * 32 + 255) / 256, 256>>>(bl[layer], 64 * (layer + 1));
    }

    colsum_kernel<<<256, 256>>>();
    post_kernel<<<1, 256>>>(post_w1, post_b1, post_w2, post_b2, post_w3, post_b3,
                            post_w4, post_b4, out);
}

// round 6
// speedup vs baseline: 1.3248x; 1.3248x over previous
#include <cuda_runtime.h>
#include <cuda_bf16.h>
#include <math.h>
#include <stdint.h>

#define NN 50000
#define EE 800000

// ================= scratch (device globals) =================
__device__ uint32_t g_x2[(size_t)NN * 128];    // node_features split (hi,lo u32 pairs)
__device__ uint32_t g_t2[(size_t)NN * 64];     // pre-mlp intermediate, split
__device__ uint32_t g_emb2[(size_t)NN * 256];  // [x|h1|h2|h3] split storage
__device__ float    g_yr[(size_t)NN * 128];    // per-layer [y | r] fp32
__device__ __align__(16) unsigned short g_Bp[2 * 192 * 128];  // B frags interleaved [bh0,bh1,bl0,bl1]
__device__ int   g_cnt[NN];
__device__ int   g_rowptr[NN];
__device__ int   g_cursor[NN];
__device__ int   g_csr_src[EE];
__device__ float g_invdeg[NN];
__device__ int   g_part[256];
__device__ float g_s[256];

__device__ __forceinline__ void split2(float x, float y, uint32_t& hi, uint32_t& lo) {
    __nv_bfloat16 hx = __float2bfloat16(x), hy = __float2bfloat16(y);
    __nv_bfloat16 lx = __float2bfloat16(x - __bfloat162float(hx));
    __nv_bfloat16 ly = __float2bfloat16(y - __bfloat162float(hy));
    hi = ((uint32_t)__bfloat16_as_ushort(hy) << 16) | __bfloat16_as_ushort(hx);
    lo = ((uint32_t)__bfloat16_as_ushort(ly) << 16) | __bfloat16_as_ushort(lx);
}

// ================= CSR build =================
__global__ void zero_kernel() {
    int i = blockIdx.x * blockDim.x + threadIdx.x;
    if (i < NN) g_cnt[i] = 0;
    if (i < 256) g_s[i] = 0.f;
}
__global__ void hist_kernel(const int* __restrict__ ei) {
    int e = blockIdx.x * blockDim.x + threadIdx.x;
    if (e < EE) atomicAdd(&g_cnt[ei[EE + e]], 1);
}
// phase 1: per-block sums (coalesced)
__global__ void part_kernel() {
    __shared__ int s[256];
    int t = threadIdx.x, b = blockIdx.x;
    int i = b * 256 + t;
    int v = (i < NN) ? g_cnt[i] : 0;
    s[t] = v;
    __syncthreads();
    for (int off = 128; off > 0; off >>= 1) {
        if (t < off) s[t] += s[t + off];
        __syncthreads();
    }
    if (t == 0) g_part[b] = s[0];
}
// phase 2: scan 196 block sums -> exclusive bases
__global__ void scanp_kernel(int nb) {
    __shared__ int s[256];
    int t = threadIdx.x;
    int v = (t < nb) ? g_part[t] : 0;
    s[t] = v;
    __syncthreads();
    for (int off = 1; off < 256; off <<= 1) {
        int add = (t >= off) ? s[t - off] : 0;
        __syncthreads();
        s[t] += add;
        __syncthreads();
    }
    if (t < nb) g_part[t] = s[t] - v;  // exclusive
}
// phase 3: local scan + fill (coalesced)
__global__ void fill_kernel() {
    __shared__ int s[256];
    int t = threadIdx.x, b = blockIdx.x;
    int i = b * 256 + t;
    int v = (i < NN) ? g_cnt[i] : 0;
    s[t] = v;
    __syncthreads();
    for (int off = 1; off < 256; off <<= 1) {
        int add = (t >= off) ? s[t - off] : 0;
        __syncthreads();
        s[t] += add;
        __syncthreads();
    }
    if (i < NN) {
        int base = g_part[b] + s[t] - v;  // exclusive prefix
        g_rowptr[i] = base;
        g_cursor[i] = base;
        g_invdeg[i] = 1.0f / (float)(v > 1 ? v : 1);
    }
}
__global__ void scatter_kernel(const int* __restrict__ ei) {
    int e = blockIdx.x * blockDim.x + threadIdx.x;
    if (e < EE) {
        int dst = ei[EE + e];
        int pos = atomicAdd(&g_cursor[dst], 1);
        g_csr_src[pos] = ei[e];
    }
}

// ================= convert node_features to split storage =================
__global__ void convertX_kernel(const float* __restrict__ X) {
    int idx = blockIdx.x * blockDim.x + threadIdx.x;  // pair index
    if (idx >= NN * 64) return;
    int row = idx >> 6, j = idx & 63;
    float2 v = *(const float2*)&X[(size_t)row * 128 + 2 * j];
    uint32_t hi, lo;
    split2(v.x, v.y, hi, lo);
    *(uint2*)&g_x2[(size_t)row * 128 + 2 * j] = make_uint2(hi, lo);
}

// ================= pack B into interleaved uint4 fragments =================
__global__ void packB_kernel(const float* __restrict__ wl, const float* __restrict__ wr,
                             const float* __restrict__ skip, int layer, int K, int NTILE) {
    int idx = blockIdx.x * blockDim.x + threadIdx.x;
    if (idx >= K * NTILE) return;
    int k = idx / NTILE, n = idx - k * NTILE;
    float w;
    if (wr) {
        float g = 1.f / (1.f + expf(-skip[layer * 3 + (k >> 6)]));
        w = ((n < 64) ? wl[k * 64 + n] : wr[k * 64 + (n - 64)]) * g;
    } else {
        w = wl[k * NTILE + n];
    }
    int kc = k >> 4, kin = k & 15, nc = n >> 3, nin = n & 7;
    int lane = nin * 4 + ((kin & 7) >> 1);
    int reg = kin >> 3, half = kin & 1;
    int base = ((kc * (NTILE >> 3) + nc) * 32 + lane) * 4;  // u32 index of frag
    __nv_bfloat16 hi = __float2bfloat16(w);
    __nv_bfloat16 lo = __float2bfloat16(w - __bfloat162float(hi));
    g_Bp[(base + reg) * 2 + half]     = __bfloat16_as_ushort(hi);
    g_Bp[(base + 2 + reg) * 2 + half] = __bfloat16_as_ushort(lo);
}

// ================= HMMA GEMM on pre-split inputs =================
__device__ __forceinline__ void mma16816(float* acc, const uint32_t* a,
                                         uint32_t b0, uint32_t b1) {
    asm volatile(
        "mma.sync.aligned.m16n8k16.row.col.f32.bf16.bf16.f32 "
        "{%0,%1,%2,%3}, {%4,%5,%6,%7}, {%8,%9}, {%0,%1,%2,%3};"
        : "+f"(acc[0]), "+f"(acc[1]), "+f"(acc[2]), "+f"(acc[3])
        : "r"(a[0]), "r"(a[1]), "r"(a[2]), "r"(a[3]), "r"(b0), "r"(b1));
}

// OUTSPLIT=1: write split u32 pairs (ldc in u32); OUTSPLIT=0: fp32 float2 (ldc in floats)
template <int NTILE, int OUTSPLIT>
__global__ void __launch_bounds__(256) mma_gemm2(
    const uint32_t* __restrict__ A2, int ldu, int K,
    const float* __restrict__ bias, int act,
    void* __restrict__ Cout, int ldc, int M) {
    constexpr int NFRAG = NTILE / 8;
    const int tid = threadIdx.x;
    const int wid = tid >> 5, lane = tid & 31;
    const int q = lane & 3, tq = lane >> 2;
    const int r0 = blockIdx.x * 128 + wid * 16 + tq;
    const int r1 = r0 + 8;

    float acc[NFRAG][4];
#pragma unroll
    for (int i = 0; i < NFRAG; i++)
#pragma unroll
        for (int j = 0; j < 4; j++) acc[i][j] = 0.f;

    const uint4* __restrict__ Bp = (const uint4*)g_Bp;

    for (int kc = 0; kc < K / 16; kc++) {
        const int c0 = kc * 16 + 2 * q;
        uint2 p00 = make_uint2(0u, 0u), p01 = p00, p10 = p00, p11 = p00;
        if (r0 < M) {
            p00 = *(const uint2*)&A2[(size_t)r0 * ldu + c0];
            p01 = *(const uint2*)&A2[(size_t)r0 * ldu + c0 + 8];
        }
        if (r1 < M) {
            p10 = *(const uint2*)&A2[(size_t)r1 * ldu + c0];
            p11 = *(const uint2*)&A2[(size_t)r1 * ldu + c0 + 8];
        }
        uint32_t ah[4] = {p00.x, p10.x, p01.x, p11.x};
        uint32_t al[4] = {p00.y, p10.y, p01.y, p11.y};

        const uint4* bp = Bp + (size_t)(kc * NFRAG) * 32 + lane;
#pragma unroll
        for (int nc = 0; nc < NFRAG; nc++) {
            uint4 b = bp[nc * 32];
            mma16816(acc[nc], ah, b.x, b.y);
            mma16816(acc[nc], ah, b.z, b.w);
            mma16816(acc[nc], al, b.x, b.y);
        }
    }

#pragma unroll
    for (int nc = 0; nc < NFRAG; nc++) {
        int col = nc * 8 + 2 * q;
        float b0v = bias ? bias[col] : 0.f;
        float b1v = bias ? bias[col + 1] : 0.f;
        float x0 = acc[nc][0] + b0v, y0 = acc[nc][1] + b1v;
        float x1 = acc[nc][2] + b0v, y1 = acc[nc][3] + b1v;
        if (act) {
            x0 = fmaxf(x0, 0.f); y0 = fmaxf(y0, 0.f);
            x1 = fmaxf(x1, 0.f); y1 = fmaxf(y1, 0.f);
        }
        if (OUTSPLIT) {
            uint32_t* Cu = (uint32_t*)Cout;
            uint32_t hi, lo;
            if (r0 < M) {
                split2(x0, y0, hi, lo);
                *(uint2*)&Cu[(size_t)r0 * ldc + col] = make_uint2(hi, lo);
            }
            if (r1 < M) {
                split2(x1, y1, hi, lo);
                *(uint2*)&Cu[(size_t)r1 * ldc + col] = make_uint2(hi, lo);
            }
        } else {
            float* Cf = (float*)Cout;
            if (r0 < M) *(float2*)&Cf[(size_t)r0 * ldc + col] = make_float2(x0, y0);
            if (r1 < M) *(float2*)&Cf[(size_t)r1 * ldc + col] = make_float2(x1, y1);
        }
    }
}

// ================= aggregation: one warp per node =================
__global__ void agg_kernel(const float* __restrict__ bl, int outcol) {
    int gw = (blockIdx.x * blockDim.x + threadIdx.x) >> 5;
    int lane = threadIdx.x & 31;
    if (gw >= NN) return;
    const int n = gw;
    const int beg = g_rowptr[n], cnt = g_cnt[n];
    const float* __restrict__ yr = g_yr;
    float sx = 0.f, sy = 0.f;
    for (int k = 0; k < cnt; k++) {
        int src = g_csr_src[beg + k];
        float2 v = *reinterpret_cast<const float2*>(&yr[(size_t)src * 128 + 2 * lane]);
        sx += v.x;
        sy += v.y;
    }
    float inv = g_invdeg[n];
    float2 r = *reinterpret_cast<const float2*>(&yr[(size_t)n * 128 + 64 + 2 * lane]);
    float h0 = fmaxf(sx * inv + bl[2 * lane] + r.x, 0.f);
    float h1 = fmaxf(sy * inv + bl[2 * lane + 1] + r.y, 0.f);
    uint32_t hi, lo;
    split2(h0, h1, hi, lo);
    *(uint2*)&g_emb2[(size_t)n * 256 + outcol + 2 * lane] = make_uint2(hi, lo);
}

// ================= column sum over split emb + post mlp =================
__global__ void colsum_kernel() {
    int t = threadIdx.x;  // 128 threads: col pair (2t, 2t+1)
    int per = (NN + gridDim.x - 1) / gridDim.x;
    int n0 = blockIdx.x * per;
    int n1 = n0 + per;
    if (n1 > NN) n1 = NN;
    float s0 = 0.f, s1 = 0.f;
    for (int n = n0; n < n1; n++) {
        uint2 w = *(const uint2*)&g_emb2[(size_t)n * 256 + 2 * t];
        s0 += __uint_as_float(w.x << 16) + __uint_as_float(w.y << 16);
        s1 += __uint_as_float(w.x & 0xFFFF0000u) + __uint_as_float(w.y & 0xFFFF0000u);
    }
    atomicAdd(&g_s[2 * t], s0);
    atomicAdd(&g_s[2 * t + 1], s1);
}
__global__ void post_kernel(const float* __restrict__ w1, const float* __restrict__ b1,
                            const float* __restrict__ w2, const float* __restrict__ b2,
                            const float* __restrict__ w3, const float* __restrict__ b3,
                            const float* __restrict__ w4, const float* __restrict__ b4,
                            float* __restrict__ out) {
    __shared__ float s1[64], s2[64], s3[256];
    int t = threadIdx.x;
    if (t < 64) {
        float a = b1[t];
        for (int k = 0; k < 256; k++) a += g_s[k] * w1[k * 64 + t];
        s1[t] = (a > 0.f) ? a : 0.1f * a;
    }
    __syncthreads();
    if (t < 64) {
        float a = b2[t];
        for (int k = 0; k < 64; k++) a += s1[k] * w2[k * 64 + t];
        s2[t] = fmaxf(a, 0.f);
    }
    __syncthreads();
    {
        float a = b3[t];
        for (int k = 0; k < 64; k++) a += s2[k] * w3[k * 256 + t];
        s3[t] = fmaxf(a, 0.f);
    }
    __syncthreads();
    if (t < 64) {
        float a = b4[t];
        for (int k = 0; k < 256; k++) a += s3[k] * w4[k * 64 + t];
        out[t] = a;
    }
}

// ================= launch =================
extern "C" void kernel_launch(void* const* d_in, const int* in_sizes, int n_in,
                              void* d_out, int out_size) {
    const float* node_features = (const float*)d_in[0];
    const int*   edge_index    = (const int*)d_in[1];
    const float* pre_w1 = (const float*)d_in[2];
    const float* pre_b1 = (const float*)d_in[3];
    const float* pre_w2 = (const float*)d_in[4];
    const float* pre_b2 = (const float*)d_in[5];
    const float* skip   = (const float*)d_in[6];
    const float* wl[3] = {(const float*)d_in[7], (const float*)d_in[10], (const float*)d_in[13]};
    const float* bl[3] = {(const float*)d_in[8], (const float*)d_in[11], (const float*)d_in[14]};
    const float* wr[3] = {(const float*)d_in[9], (const float*)d_in[12], (const float*)d_in[15]};
    const float* post_w1 = (const float*)d_in[16];
    const float* post_b1 = (const float*)d_in[17];
    const float* post_w2 = (const float*)d_in[18];
    const float* post_b2 = (const float*)d_in[19];
    const float* post_w3 = (const float*)d_in[20];
    const float* post_b3 = (const float*)d_in[21];
    const float* post_w4 = (const float*)d_in[22];
    const float* post_b4 = (const float*)d_in[23];
    float* out = (float*)d_out;

    uint32_t *p_x2, *p_t2, *p_emb2;
    float* p_yr;
    cudaGetSymbolAddress((void**)&p_x2, g_x2);
    cudaGetSymbolAddress((void**)&p_t2, g_t2);
    cudaGetSymbolAddress((void**)&p_emb2, g_emb2);
    cudaGetSymbolAddress((void**)&p_yr, g_yr);

    const int NB = (NN + 255) / 256;  // 196

    // CSR build (coalesced 3-phase scan)
    zero_kernel<<<NB, 256>>>();
    hist_kernel<<<(EE + 255) / 256, 256>>>(edge_index);
    part_kernel<<<NB, 256>>>();
    scanp_kernel<<<1, 256>>>(NB);
    fill_kernel<<<NB, 256>>>();
    scatter_kernel<<<(EE + 255) / 256, 256>>>(edge_index);

    // split node features
    convertX_kernel<<<(NN * 64 + 255) / 256, 256>>>(node_features);

    const int MB = (NN + 127) / 128;  // 391

    // pre-mlp GEMM 1: t2 = relu(X @ pre_w1 + b1), K=128 N=64, split out
    packB_kernel<<<(128 * 64 + 255) / 256, 256>>>(pre_w1, nullptr, nullptr, 0, 128, 64);
    mma_gemm2<64, 1><<<MB, 256>>>(p_x2, 128, 128, pre_b1, 1, p_t2, 64, NN);
    // pre-mlp GEMM 2: emb2[:,0:64] = t @ pre_w2 + b2, K=64 N=64, split out
    packB_kernel<<<(64 * 64 + 255) / 256, 256>>>(pre_w2, nullptr, nullptr, 0, 64, 64);
    mma_gemm2<64, 1><<<MB, 256>>>(p_t2, 64, 64, pre_b2, 0, p_emb2, 256, NN);

    for (int layer = 0; layer < 3; layer++) {
        int K = 64 * (layer + 1);
        packB_kernel<<<(K * 128 + 255) / 256, 256>>>(wl[layer], wr[layer], skip, layer, K, 128);
        mma_gemm2<128, 0><<<MB, 256>>>(p_emb2, 256, K, (const float*)nullptr, 0, p_yr, 128, NN);
        agg_kernel<<<(NN * 32 + 255) / 256, 256>>>(bl[layer], 64 * (layer + 1));
    }

    colsum_kernel<<<256, 128>>>();
    post_kernel<<<1, 256>>>(post_w1, post_b1, post_w2, post_b2, post_w3, post_b3,
                            post_w4, post_b4, out);
}